// round 2
// baseline (speedup 1.0000x reference)
#include <cuda_runtime.h>
#include <cuda_bf16.h>
#include <math.h>

// ---------------- problem constants (fixed by setup_inputs) ----------------
#define S_LEN 4032      // F*H*W = 9*16*28
#define DIMN  1536
#define NHEAD 12
#define HD    128
#define FF    9
#define HHG   16
#define WWG   28
#define CF    22        // C_F
#define CHH   21        // C_H
#define CWW   21        // C_W

// ---------------- scratch (static device globals; no allocations) ----------
__device__ float g_Q[S_LEN * DIMN];
__device__ float g_K[S_LEN * DIMN];
__device__ float g_V[S_LEN * DIMN];
__device__ float g_O[S_LEN * DIMN];

// ============================================================================
// GEMM: C[M,N] = A[M,K] @ B[N,K]^T + bias[N]     (row-major A, row-major B)
// Tile: BM=64, BN=128, BK=16. 256 threads, 4x8 microtile per thread.
// ============================================================================
__global__ __launch_bounds__(256) void gemm_abt_bias(
    const float* __restrict__ A, const float* __restrict__ B,
    const float* __restrict__ bias, float* __restrict__ C,
    int M, int N, int K)
{
    __shared__ float As[16][64];    // [k][m]
    __shared__ float Bs[16][128];   // [k][n]

    const int tid = threadIdx.x;
    const int bm = blockIdx.y * 64;
    const int bn = blockIdx.x * 128;
    const int tx = tid & 15;        // n-group
    const int ty = tid >> 4;        // m-group
    const int tn = tx * 8;
    const int tm = ty * 4;

    const int ar = tid >> 2;            // 0..63
    const int ac = (tid & 3) << 2;      // 0,4,8,12
    const int br = tid >> 1;            // 0..127
    const int bc = (tid & 1) << 3;      // 0 or 8

    float acc[4][8];
#pragma unroll
    for (int i = 0; i < 4; ++i)
#pragma unroll
        for (int j = 0; j < 8; ++j) acc[i][j] = 0.f;

    for (int k0 = 0; k0 < K; k0 += 16) {
        // load A tile (64 x 16), transposed into As[k][m]
        {
            float4 v = *(const float4*)(A + (size_t)(bm + ar) * K + k0 + ac);
            As[ac + 0][ar] = v.x;
            As[ac + 1][ar] = v.y;
            As[ac + 2][ar] = v.z;
            As[ac + 3][ar] = v.w;
        }
        // load B tile (128 x 16), transposed into Bs[k][n]
        {
            float4 v0 = *(const float4*)(B + (size_t)(bn + br) * K + k0 + bc);
            float4 v1 = *(const float4*)(B + (size_t)(bn + br) * K + k0 + bc + 4);
            Bs[bc + 0][br] = v0.x;
            Bs[bc + 1][br] = v0.y;
            Bs[bc + 2][br] = v0.z;
            Bs[bc + 3][br] = v0.w;
            Bs[bc + 4][br] = v1.x;
            Bs[bc + 5][br] = v1.y;
            Bs[bc + 6][br] = v1.z;
            Bs[bc + 7][br] = v1.w;
        }
        __syncthreads();

#pragma unroll
        for (int k = 0; k < 16; ++k) {
            float a0 = As[k][tm + 0];
            float a1 = As[k][tm + 1];
            float a2 = As[k][tm + 2];
            float a3 = As[k][tm + 3];
            float4 bv0 = *(const float4*)&Bs[k][tn];
            float4 bv1 = *(const float4*)&Bs[k][tn + 4];
            float b[8] = {bv0.x, bv0.y, bv0.z, bv0.w, bv1.x, bv1.y, bv1.z, bv1.w};
#pragma unroll
            for (int j = 0; j < 8; ++j) {
                acc[0][j] = fmaf(a0, b[j], acc[0][j]);
                acc[1][j] = fmaf(a1, b[j], acc[1][j]);
                acc[2][j] = fmaf(a2, b[j], acc[2][j]);
                acc[3][j] = fmaf(a3, b[j], acc[3][j]);
            }
        }
        __syncthreads();
    }

    // epilogue: add bias, write
    float4 bb0 = *(const float4*)(bias + bn + tn);
    float4 bb1 = *(const float4*)(bias + bn + tn + 4);
#pragma unroll
    for (int i = 0; i < 4; ++i) {
        float4 r0, r1;
        r0.x = acc[i][0] + bb0.x; r0.y = acc[i][1] + bb0.y;
        r0.z = acc[i][2] + bb0.z; r0.w = acc[i][3] + bb0.w;
        r1.x = acc[i][4] + bb1.x; r1.y = acc[i][5] + bb1.y;
        r1.z = acc[i][6] + bb1.z; r1.w = acc[i][7] + bb1.w;
        float* dst = C + (size_t)(bm + tm + i) * N + bn + tn;
        *(float4*)dst = r0;
        *(float4*)(dst + 4) = r1;
    }
}

// ============================================================================
// Fused RMSNorm (over full DIM) + 3D RoPE for Q and K. One block per token.
// 256 threads, each owning 6 consecutive elements (3 rope pairs).
// ============================================================================
__global__ __launch_bounds__(256) void rmsrope_kernel(
    float* __restrict__ Qm, float* __restrict__ Km,
    const float* __restrict__ gq, const float* __restrict__ gk,
    const float* __restrict__ cf, const float* __restrict__ sf,
    const float* __restrict__ ch, const float* __restrict__ sh,
    const float* __restrict__ cw, const float* __restrict__ sw)
{
    const int s = blockIdx.x;
    const int tid = threadIdx.x;

    const int f  = s / (HHG * WWG);
    const int rm = s - f * (HHG * WWG);
    const int hh = rm / WWG;
    const int ww = rm - hh * WWG;

    // cos/sin for this thread's 3 pairs (same for all heads; c = pair % 64)
    float co[3], si[3];
#pragma unroll
    for (int p = 0; p < 3; ++p) {
        int c = (tid * 3 + p) & 63;
        if (c < CF)            { co[p] = cf[f  * CF  + c];             si[p] = sf[f  * CF  + c]; }
        else if (c < CF + CHH) { co[p] = ch[hh * CHH + (c - CF)];      si[p] = sh[hh * CHH + (c - CF)]; }
        else                   { co[p] = cw[ww * CWW + (c - CF - CHH)];si[p] = sw[ww * CWW + (c - CF - CHH)]; }
    }

    __shared__ float red[8];
    __shared__ float bcast;

    for (int which = 0; which < 2; ++which) {
        float* T = which ? Km : Qm;
        const float* g = which ? gk : gq;
        const size_t base = (size_t)s * DIMN + tid * 6;

        float v[6];
#pragma unroll
        for (int p = 0; p < 3; ++p) {
            float2 t = *(const float2*)(T + base + 2 * p);
            v[2 * p] = t.x; v[2 * p + 1] = t.y;
        }
        float ss = 0.f;
#pragma unroll
        for (int e = 0; e < 6; ++e) ss += v[e] * v[e];
        for (int off = 16; off; off >>= 1) ss += __shfl_xor_sync(0xffffffffu, ss, off);
        if ((tid & 31) == 0) red[tid >> 5] = ss;
        __syncthreads();
        if (tid < 32) {
            float t = (tid < 8) ? red[tid] : 0.f;
            for (int off = 4; off; off >>= 1) t += __shfl_xor_sync(0xffffffffu, t, off);
            if (tid == 0) bcast = t;
        }
        __syncthreads();
        const float rinv = rsqrtf(bcast * (1.0f / DIMN) + 1e-6f);

#pragma unroll
        for (int p = 0; p < 3; ++p) {
            float e = v[2 * p]     * rinv * g[tid * 6 + 2 * p];
            float o = v[2 * p + 1] * rinv * g[tid * 6 + 2 * p + 1];
            float2 r;
            r.x = e * co[p] - o * si[p];
            r.y = e * si[p] + o * co[p];
            *(float2*)(T + base + 2 * p) = r;
        }
        __syncthreads();    // protect red/bcast reuse
    }
}

// ============================================================================
// Flash attention (fp32, non-causal). grid = (S/64, NHEAD), 256 threads.
// BQ = BK = 64, D = 128. smem: Qs(32K) + KV(32K, K then V) + Ps(16K) = 80 KB.
// XOR swizzle on float4 chunks: chunk' = chunk ^ ((row>>2)&7)  (conflict-free).
// ============================================================================
#define FLASH_SMEM ((64 * 128 * 2 + 64 * 64) * 4)

__global__ __launch_bounds__(256, 2) void flash_kernel(
    const float* __restrict__ Q, const float* __restrict__ K,
    const float* __restrict__ V, float* __restrict__ O)
{
    extern __shared__ float sm[];
    float* Qs = sm;                 // [64][128] swizzled
    float* KV = sm + 64 * 128;      // [64][128] swizzled (K, then V)
    float* Ps = KV + 64 * 128;      // [64][64]

    const int tid = threadIdx.x;
    const int tx = tid & 15;        // score-col group / out-col group
    const int ty = tid >> 4;        // row group
    const int h  = blockIdx.y;
    const int q0 = blockIdx.x * 64;

    // ---- load Q tile (swizzled) ----
    {
        const float* src = Q + (size_t)q0 * DIMN + h * HD;
#pragma unroll
        for (int it = 0; it < 8; ++it) {
            int idx = tid + it * 256;
            int r = idx >> 5;
            int c = idx & 31;
            float4 v = *(const float4*)(src + (size_t)r * DIMN + (c << 2));
            *(float4*)(Qs + r * 128 + ((c ^ ((r >> 2) & 7)) << 2)) = v;
        }
    }

    float m_i[4], l_i[4], o[4][8];
#pragma unroll
    for (int i = 0; i < 4; ++i) {
        m_i[i] = -1e30f; l_i[i] = 0.f;
#pragma unroll
        for (int j = 0; j < 8; ++j) o[i][j] = 0.f;
    }

    const float scale = 0.08838834764831845f;   // 1/sqrt(128)
    const int akey = ty & 7;                    // (row>>2)&7 for rows ty*4..ty*4+3
    const int bkey = tx & 7;
    const int aBase = (ty * 4) * 128;
    const int bBase = (tx * 4) * 128;

    for (int kt = 0; kt < S_LEN / 64; ++kt) {
        __syncthreads();    // prior V/Ps fully consumed; Qs visible on first iter
        // ---- load K tile ----
        {
            const float* src = K + (size_t)(kt * 64) * DIMN + h * HD;
#pragma unroll
            for (int it = 0; it < 8; ++it) {
                int idx = tid + it * 256;
                int r = idx >> 5;
                int c = idx & 31;
                float4 v = *(const float4*)(src + (size_t)r * DIMN + (c << 2));
                *(float4*)(KV + r * 128 + ((c ^ ((r >> 2) & 7)) << 2)) = v;
            }
        }
        __syncthreads();

        // ---- scores S = Q K^T (4x4 microtile) ----
        float s4[4][4];
#pragma unroll
        for (int i = 0; i < 4; ++i)
#pragma unroll
            for (int j = 0; j < 4; ++j) s4[i][j] = 0.f;

#pragma unroll 4
        for (int dc = 0; dc < 32; ++dc) {
            const int ad = (dc ^ akey) << 2;
            const int bd = (dc ^ bkey) << 2;
            float4 a0 = *(const float4*)(Qs + aBase + 0 * 128 + ad);
            float4 a1 = *(const float4*)(Qs + aBase + 1 * 128 + ad);
            float4 a2 = *(const float4*)(Qs + aBase + 2 * 128 + ad);
            float4 a3 = *(const float4*)(Qs + aBase + 3 * 128 + ad);
            float4 b0 = *(const float4*)(KV + bBase + 0 * 128 + bd);
            float4 b1 = *(const float4*)(KV + bBase + 1 * 128 + bd);
            float4 b2 = *(const float4*)(KV + bBase + 2 * 128 + bd);
            float4 b3 = *(const float4*)(KV + bBase + 3 * 128 + bd);
            float4 aa[4] = {a0, a1, a2, a3};
            float4 bb[4] = {b0, b1, b2, b3};
#pragma unroll
            for (int i = 0; i < 4; ++i)
#pragma unroll
                for (int j = 0; j < 4; ++j) {
                    s4[i][j] = fmaf(aa[i].x, bb[j].x, s4[i][j]);
                    s4[i][j] = fmaf(aa[i].y, bb[j].y, s4[i][j]);
                    s4[i][j] = fmaf(aa[i].z, bb[j].z, s4[i][j]);
                    s4[i][j] = fmaf(aa[i].w, bb[j].w, s4[i][j]);
                }
        }

        // ---- online softmax update ----
#pragma unroll
        for (int i = 0; i < 4; ++i) {
#pragma unroll
            for (int j = 0; j < 4; ++j) s4[i][j] *= scale;
            float mt = fmaxf(fmaxf(s4[i][0], s4[i][1]), fmaxf(s4[i][2], s4[i][3]));
            for (int off = 8; off; off >>= 1)
                mt = fmaxf(mt, __shfl_xor_sync(0xffffffffu, mt, off));
            const float mn = fmaxf(m_i[i], mt);
            const float alpha = __expf(m_i[i] - mn);
            m_i[i] = mn;
            float rs = 0.f;
#pragma unroll
            for (int j = 0; j < 4; ++j) {
                s4[i][j] = __expf(s4[i][j] - mn);
                rs += s4[i][j];
            }
            for (int off = 8; off; off >>= 1)
                rs += __shfl_xor_sync(0xffffffffu, rs, off);
            l_i[i] = l_i[i] * alpha + rs;
#pragma unroll
            for (int j = 0; j < 8; ++j) o[i][j] *= alpha;
#pragma unroll
            for (int j = 0; j < 4; ++j)
                Ps[(ty * 4 + i) * 64 + tx * 4 + j] = s4[i][j];
        }
        __syncthreads();    // all K reads done & P written before V overwrites KV

        // ---- load V tile ----
        {
            const float* src = V + (size_t)(kt * 64) * DIMN + h * HD;
#pragma unroll
            for (int it = 0; it < 8; ++it) {
                int idx = tid + it * 256;
                int r = idx >> 5;
                int c = idx & 31;
                float4 v = *(const float4*)(src + (size_t)r * DIMN + (c << 2));
                *(float4*)(KV + r * 128 + ((c ^ ((r >> 2) & 7)) << 2)) = v;
            }
        }
        __syncthreads();

        // ---- O += P @ V ----
#pragma unroll 4
        for (int k = 0; k < 64; ++k) {
            const int key = (k >> 2) & 7;
            float4 v0 = *(const float4*)(KV + k * 128 + (((tx * 2)     ^ key) << 2));
            float4 v1 = *(const float4*)(KV + k * 128 + (((tx * 2 + 1) ^ key) << 2));
            float p0 = Ps[(ty * 4 + 0) * 64 + k];
            float p1 = Ps[(ty * 4 + 1) * 64 + k];
            float p2 = Ps[(ty * 4 + 2) * 64 + k];
            float p3 = Ps[(ty * 4 + 3) * 64 + k];
            float pv[4] = {p0, p1, p2, p3};
#pragma unroll
            for (int i = 0; i < 4; ++i) {
                o[i][0] = fmaf(pv[i], v0.x, o[i][0]);
                o[i][1] = fmaf(pv[i], v0.y, o[i][1]);
                o[i][2] = fmaf(pv[i], v0.z, o[i][2]);
                o[i][3] = fmaf(pv[i], v0.w, o[i][3]);
                o[i][4] = fmaf(pv[i], v1.x, o[i][4]);
                o[i][5] = fmaf(pv[i], v1.y, o[i][5]);
                o[i][6] = fmaf(pv[i], v1.z, o[i][6]);
                o[i][7] = fmaf(pv[i], v1.w, o[i][7]);
            }
        }
    }

    // ---- write O ----
    float* dst = O + (size_t)q0 * DIMN + h * HD;
#pragma unroll
    for (int i = 0; i < 4; ++i) {
        const float inv = 1.0f / l_i[i];
        float4 r0, r1;
        r0.x = o[i][0] * inv; r0.y = o[i][1] * inv;
        r0.z = o[i][2] * inv; r0.w = o[i][3] * inv;
        r1.x = o[i][4] * inv; r1.y = o[i][5] * inv;
        r1.z = o[i][6] * inv; r1.w = o[i][7] * inv;
        float* p = dst + (size_t)(ty * 4 + i) * DIMN + tx * 8;
        *(float4*)p = r0;
        *(float4*)(p + 4) = r1;
    }
}

// ============================================================================
// launch
// ============================================================================
extern "C" void kernel_launch(void* const* d_in, const int* in_sizes, int n_in,
                              void* d_out, int out_size)
{
    const float* x  = (const float*)d_in[0];
    const float* Wq = (const float*)d_in[1];
    const float* bq = (const float*)d_in[2];
    const float* Wk = (const float*)d_in[3];
    const float* bk = (const float*)d_in[4];
    const float* Wv = (const float*)d_in[5];
    const float* bv = (const float*)d_in[6];
    const float* Wo = (const float*)d_in[7];
    const float* bo = (const float*)d_in[8];
    const float* gq = (const float*)d_in[9];
    const float* gk = (const float*)d_in[10];
    const float* cf = (const float*)d_in[11];
    const float* sf = (const float*)d_in[12];
    const float* ch = (const float*)d_in[13];
    const float* sh = (const float*)d_in[14];
    const float* cw = (const float*)d_in[15];
    const float* sw = (const float*)d_in[16];
    float* out = (float*)d_out;

    float *Qd, *Kd, *Vd, *Od;
    cudaGetSymbolAddress((void**)&Qd, g_Q);
    cudaGetSymbolAddress((void**)&Kd, g_K);
    cudaGetSymbolAddress((void**)&Vd, g_V);
    cudaGetSymbolAddress((void**)&Od, g_O);

    cudaFuncSetAttribute(flash_kernel,
                         cudaFuncAttributeMaxDynamicSharedMemorySize, FLASH_SMEM);

    dim3 gblk(256);
    dim3 ggrid(DIMN / 128, S_LEN / 64);

    gemm_abt_bias<<<ggrid, gblk>>>(x, Wq, bq, Qd, S_LEN, DIMN, DIMN);
    gemm_abt_bias<<<ggrid, gblk>>>(x, Wk, bk, Kd, S_LEN, DIMN, DIMN);
    gemm_abt_bias<<<ggrid, gblk>>>(x, Wv, bv, Vd, S_LEN, DIMN, DIMN);

    rmsrope_kernel<<<S_LEN, 256>>>(Qd, Kd, gq, gk, cf, sf, ch, sh, cw, sw);

    flash_kernel<<<dim3(S_LEN / 64, NHEAD), 256, FLASH_SMEM>>>(Qd, Kd, Vd, Od);

    gemm_abt_bias<<<ggrid, gblk>>>(Od, Wo, bo, out, S_LEN, DIMN, DIMN);
}

// round 4
// speedup vs baseline: 1.5260x; 1.5260x over previous
#include <cuda_runtime.h>
#include <cuda_bf16.h>
#include <cstdint>
#include <math.h>

// ---------------- problem constants ----------------
#define S_LEN 4032
#define S_PAD 4096
#define DIMN  1536
#define NHEAD 12
#define HD    128
#define FF    9
#define HHG   16
#define WWG   28
#define CF    22
#define CHH   21
#define CWW   21

// ---------------- scratch ----------------
__device__ float g_Q[S_PAD * DIMN];
__device__ float g_K[S_PAD * DIMN];
__device__ float g_V[S_PAD * DIMN];
__device__ float g_O[S_PAD * DIMN];
__device__ unsigned short g_xh[S_PAD * DIMN], g_xl[S_PAD * DIMN];
__device__ unsigned short g_oh[S_PAD * DIMN], g_ol[S_PAD * DIMN];
__device__ unsigned short g_wqh[DIMN * DIMN], g_wql[DIMN * DIMN];
__device__ unsigned short g_wkh[DIMN * DIMN], g_wkl[DIMN * DIMN];
__device__ unsigned short g_wvh[DIMN * DIMN], g_wvl[DIMN * DIMN];
__device__ unsigned short g_woh[DIMN * DIMN], g_wol[DIMN * DIMN];

// ---------------- helpers ----------------
__device__ __forceinline__ uint32_t smem_to_u32(const void* p) {
    uint32_t a;
    asm("{ .reg .u64 t; cvta.to.shared.u64 t, %1; cvt.u32.u64 %0, t; }" : "=r"(a) : "l"(p));
    return a;
}
#define SWZ128(off) ((off) ^ (((off) >> 3) & 0x70))

__device__ __forceinline__ void ldsm_x4(uint32_t* r, uint32_t addr) {
    asm volatile("ldmatrix.sync.aligned.m8n8.x4.shared.b16 {%0,%1,%2,%3}, [%4];"
                 : "=r"(r[0]), "=r"(r[1]), "=r"(r[2]), "=r"(r[3]) : "r"(addr));
}
__device__ __forceinline__ void ldsm_x2(uint32_t* r, uint32_t addr) {
    asm volatile("ldmatrix.sync.aligned.m8n8.x2.shared.b16 {%0,%1}, [%2];"
                 : "=r"(r[0]), "=r"(r[1]) : "r"(addr));
}
__device__ __forceinline__ void mma_bf16(float* c, const uint32_t* a, const uint32_t* b) {
    asm volatile("mma.sync.aligned.m16n8k16.row.col.f32.bf16.bf16.f32 "
                 "{%0,%1,%2,%3}, {%4,%5,%6,%7}, {%8,%9}, {%0,%1,%2,%3};"
                 : "+f"(c[0]), "+f"(c[1]), "+f"(c[2]), "+f"(c[3])
                 : "r"(a[0]), "r"(a[1]), "r"(a[2]), "r"(a[3]), "r"(b[0]), "r"(b[1]));
}

// ============================================================================
// split fp32 -> bf16 hi/lo (with zero-padding beyond n_valid)
// ============================================================================
__global__ __launch_bounds__(256) void split_kernel(
    const float* __restrict__ src, unsigned short* __restrict__ hi,
    unsigned short* __restrict__ lo, int n_valid, int n_total)
{
    int i = (blockIdx.x * 256 + threadIdx.x) * 2;
    if (i >= n_total) return;
    float2 v = (i < n_valid) ? *(const float2*)(src + i) : make_float2(0.f, 0.f);
    __nv_bfloat16 h0 = __float2bfloat16_rn(v.x);
    __nv_bfloat16 h1 = __float2bfloat16_rn(v.y);
    __nv_bfloat16 l0 = __float2bfloat16_rn(v.x - __bfloat162float(h0));
    __nv_bfloat16 l1 = __float2bfloat16_rn(v.y - __bfloat162float(h1));
    unsigned int hp = ((unsigned int)*(unsigned short*)&h1 << 16) | *(unsigned short*)&h0;
    unsigned int lp = ((unsigned int)*(unsigned short*)&l1 << 16) | *(unsigned short*)&l0;
    *(unsigned int*)(hi + i) = hp;
    *(unsigned int*)(lo + i) = lp;
}

// ============================================================================
// mma.sync bf16x3 GEMM: C[M,N] = A[M,K] @ B[N,K]^T + bias
// BM=128, BN=128, BK=64. 256 threads (8 warps, 2x4), warp tile 64x32.
// smem: Ah/Al/Bh/Bl, each [128 rows][64 bf16 = 128B], SW128 xor swizzle.
// ============================================================================
#define SM_AH  0
#define SM_AL  16384
#define SM_BH  32768
#define SM_BL  49152
#define GEMM_SMEM 65536
#define NCHUNK (DIMN / 64)

__global__ __launch_bounds__(256, 2) void gemm_tc(
    const unsigned short* __restrict__ Ahi, const unsigned short* __restrict__ Alo,
    const unsigned short* __restrict__ Bhi, const unsigned short* __restrict__ Blo,
    const float* __restrict__ bias, float* __restrict__ C, int Mvalid)
{
    extern __shared__ __align__(1024) char smem[];
    const uint32_t sb = smem_to_u32(smem);
    const int tid  = threadIdx.x;
    const int lane = tid & 31;
    const int wid  = tid >> 5;
    const int wm   = wid & 1;       // 0..1 -> m offset 0/64
    const int wn   = wid >> 1;      // 0..3 -> n offset 0/32/64/96
    const int bm = blockIdx.y * 128;
    const int bn = blockIdx.x * 128;

    // gmem->smem load coords (per 128x64 bf16 tile = 1024 uint4, 4/thread)
    const int r0 = tid >> 3;                 // 0..31
    const int c8 = tid & 7;                  // 16B chunk in 128B row
    const uint32_t st_off = SWZ128((uint32_t)(r0 * 128 + c8 * 16));

    // ldmatrix address precompute
    uint32_t aoff[4], akey[4];
#pragma unroll
    for (int mf = 0; mf < 4; ++mf) {
        int arow = wm * 64 + mf * 16 + (lane & 15);
        aoff[mf] = (uint32_t)(arow * 128);
        akey[mf] = (uint32_t)((arow & 7) << 4);
    }
    uint32_t boff[4], bkey[4];
    {
        int l = lane & 15;
#pragma unroll
        for (int nf = 0; nf < 4; ++nf) {
            int brow = wn * 32 + nf * 8 + (l & 7);
            boff[nf] = (uint32_t)(brow * 128);
            bkey[nf] = (uint32_t)((brow & 7) << 4);
        }
    }
    const uint32_t abit = (uint32_t)((lane >> 4) << 4);          // 0 or 16
    const uint32_t bbit = (uint32_t)((((lane & 15) >> 3) & 1) << 4);

    float acc[4][4][4];
#pragma unroll
    for (int mf = 0; mf < 4; ++mf)
#pragma unroll
        for (int nf = 0; nf < 4; ++nf)
#pragma unroll
            for (int e = 0; e < 4; ++e) acc[mf][nf][e] = 0.f;

    for (int chunk = 0; chunk < NCHUNK; ++chunk) {
        const int k0 = chunk * 64;
        __syncthreads();    // previous chunk's mma reads done
        // ---- load 4 tiles ----
        {
            const unsigned short* srcs[4] = {Ahi, Alo, Bhi, Blo};
            const int rowbase[4] = {bm, bm, bn, bn};
            const uint32_t dsts[4] = {SM_AH, SM_AL, SM_BH, SM_BL};
#pragma unroll
            for (int t = 0; t < 4; ++t) {
                const unsigned short* s = srcs[t] + (size_t)(rowbase[t] + r0) * DIMN + k0 + c8 * 8;
                char* d = smem + dsts[t] + st_off;
#pragma unroll
                for (int i = 0; i < 4; ++i)
                    *(uint4*)(d + i * 4096) = *(const uint4*)(s + (size_t)(i * 32) * DIMN);
            }
        }
        __syncthreads();

        // ---- mma over 4 k16 steps ----
#pragma unroll
        for (int ks = 0; ks < 4; ++ks) {
            const uint32_t kb = (uint32_t)(ks * 32);
            uint32_t bh[4][2], bl[4][2];
#pragma unroll
            for (int nf = 0; nf < 4; ++nf) {
                uint32_t ad = sb + SM_BH + boff[nf] + ((kb + bbit) ^ bkey[nf]);
                ldsm_x2(bh[nf], ad);
                ldsm_x2(bl[nf], ad + (SM_BL - SM_BH));
            }
#pragma unroll
            for (int mf = 0; mf < 4; ++mf) {
                uint32_t ah[4], al[4];
                uint32_t ad = sb + SM_AH + aoff[mf] + ((kb + abit) ^ akey[mf]);
                ldsm_x4(ah, ad);
                ldsm_x4(al, ad + (SM_AL - SM_AH));
#pragma unroll
                for (int nf = 0; nf < 4; ++nf) {
                    mma_bf16(acc[mf][nf], ah, bh[nf]);
                    mma_bf16(acc[mf][nf], ah, bl[nf]);
                    mma_bf16(acc[mf][nf], al, bh[nf]);
                }
            }
        }
    }

    // ---- epilogue ----
    const int row0 = bm + wm * 64 + (lane >> 2);
    const int col0 = bn + wn * 32 + (lane & 3) * 2;
#pragma unroll
    for (int nf = 0; nf < 4; ++nf) {
        const int c = col0 + nf * 8;
        const float2 bb = *(const float2*)(bias + c);
#pragma unroll
        for (int mf = 0; mf < 4; ++mf) {
            const int r = row0 + mf * 16;
            if (r < Mvalid) {
                float2 v; v.x = acc[mf][nf][0] + bb.x; v.y = acc[mf][nf][1] + bb.y;
                *(float2*)(C + (size_t)r * DIMN + c) = v;
            }
            if (r + 8 < Mvalid) {
                float2 v; v.x = acc[mf][nf][2] + bb.x; v.y = acc[mf][nf][3] + bb.y;
                *(float2*)(C + (size_t)(r + 8) * DIMN + c) = v;
            }
        }
    }
}

// ============================================================================
// Fused RMSNorm + 3D RoPE for Q and K (unchanged)
// ============================================================================
__global__ __launch_bounds__(256) void rmsrope_kernel(
    float* __restrict__ Qm, float* __restrict__ Km,
    const float* __restrict__ gq, const float* __restrict__ gk,
    const float* __restrict__ cf, const float* __restrict__ sf,
    const float* __restrict__ ch, const float* __restrict__ sh,
    const float* __restrict__ cw, const float* __restrict__ sw)
{
    const int s = blockIdx.x;
    const int tid = threadIdx.x;
    const int f  = s / (HHG * WWG);
    const int rm = s - f * (HHG * WWG);
    const int hh = rm / WWG;
    const int ww = rm - hh * WWG;

    float co[3], si[3];
#pragma unroll
    for (int p = 0; p < 3; ++p) {
        int c = (tid * 3 + p) & 63;
        if (c < CF)            { co[p] = cf[f  * CF  + c];              si[p] = sf[f  * CF  + c]; }
        else if (c < CF + CHH) { co[p] = ch[hh * CHH + (c - CF)];       si[p] = sh[hh * CHH + (c - CF)]; }
        else                   { co[p] = cw[ww * CWW + (c - CF - CHH)]; si[p] = sw[ww * CWW + (c - CF - CHH)]; }
    }

    __shared__ float red[8];
    __shared__ float bcast;

    for (int which = 0; which < 2; ++which) {
        float* T = which ? Km : Qm;
        const float* g = which ? gk : gq;
        const size_t base = (size_t)s * DIMN + tid * 6;

        float v[6];
#pragma unroll
        for (int p = 0; p < 3; ++p) {
            float2 t = *(const float2*)(T + base + 2 * p);
            v[2 * p] = t.x; v[2 * p + 1] = t.y;
        }
        float ss = 0.f;
#pragma unroll
        for (int e = 0; e < 6; ++e) ss += v[e] * v[e];
        for (int off = 16; off; off >>= 1) ss += __shfl_xor_sync(0xffffffffu, ss, off);
        if ((tid & 31) == 0) red[tid >> 5] = ss;
        __syncthreads();
        if (tid < 32) {
            float t = (tid < 8) ? red[tid] : 0.f;
            for (int off = 4; off; off >>= 1) t += __shfl_xor_sync(0xffffffffu, t, off);
            if (tid == 0) bcast = t;
        }
        __syncthreads();
        const float rinv = rsqrtf(bcast * (1.0f / DIMN) + 1e-6f);

#pragma unroll
        for (int p = 0; p < 3; ++p) {
            float e = v[2 * p]     * rinv * g[tid * 6 + 2 * p];
            float o = v[2 * p + 1] * rinv * g[tid * 6 + 2 * p + 1];
            float2 r;
            r.x = e * co[p] - o * si[p];
            r.y = e * si[p] + o * co[p];
            *(float2*)(T + base + 2 * p) = r;
        }
        __syncthreads();
    }
}

// ============================================================================
// Flash attention fp32 (unchanged)
// ============================================================================
#define FLASH_SMEM ((64 * 128 * 2 + 64 * 64) * 4)

__global__ __launch_bounds__(256, 2) void flash_kernel(
    const float* __restrict__ Q, const float* __restrict__ K,
    const float* __restrict__ V, float* __restrict__ O)
{
    extern __shared__ float sm[];
    float* Qs = sm;
    float* KV = sm + 64 * 128;
    float* Ps = KV + 64 * 128;

    const int tid = threadIdx.x;
    const int tx = tid & 15;
    const int ty = tid >> 4;
    const int h  = blockIdx.y;
    const int q0 = blockIdx.x * 64;

    {
        const float* src = Q + (size_t)q0 * DIMN + h * HD;
#pragma unroll
        for (int it = 0; it < 8; ++it) {
            int idx = tid + it * 256;
            int r = idx >> 5;
            int c = idx & 31;
            float4 v = *(const float4*)(src + (size_t)r * DIMN + (c << 2));
            *(float4*)(Qs + r * 128 + ((c ^ ((r >> 2) & 7)) << 2)) = v;
        }
    }

    float m_i[4], l_i[4], o[4][8];
#pragma unroll
    for (int i = 0; i < 4; ++i) {
        m_i[i] = -1e30f; l_i[i] = 0.f;
#pragma unroll
        for (int j = 0; j < 8; ++j) o[i][j] = 0.f;
    }

    const float scale = 0.08838834764831845f;
    const int akey = ty & 7;
    const int bkey = tx & 7;
    const int aBase = (ty * 4) * 128;
    const int bBase = (tx * 4) * 128;

    for (int kt = 0; kt < S_LEN / 64; ++kt) {
        __syncthreads();
        {
            const float* src = K + (size_t)(kt * 64) * DIMN + h * HD;
#pragma unroll
            for (int it = 0; it < 8; ++it) {
                int idx = tid + it * 256;
                int r = idx >> 5;
                int c = idx & 31;
                float4 v = *(const float4*)(src + (size_t)r * DIMN + (c << 2));
                *(float4*)(KV + r * 128 + ((c ^ ((r >> 2) & 7)) << 2)) = v;
            }
        }
        __syncthreads();

        float s4[4][4];
#pragma unroll
        for (int i = 0; i < 4; ++i)
#pragma unroll
            for (int j = 0; j < 4; ++j) s4[i][j] = 0.f;

#pragma unroll 4
        for (int dc = 0; dc < 32; ++dc) {
            const int ad = (dc ^ akey) << 2;
            const int bd = (dc ^ bkey) << 2;
            float4 a0 = *(const float4*)(Qs + aBase + 0 * 128 + ad);
            float4 a1 = *(const float4*)(Qs + aBase + 1 * 128 + ad);
            float4 a2 = *(const float4*)(Qs + aBase + 2 * 128 + ad);
            float4 a3 = *(const float4*)(Qs + aBase + 3 * 128 + ad);
            float4 b0 = *(const float4*)(KV + bBase + 0 * 128 + bd);
            float4 b1 = *(const float4*)(KV + bBase + 1 * 128 + bd);
            float4 b2 = *(const float4*)(KV + bBase + 2 * 128 + bd);
            float4 b3 = *(const float4*)(KV + bBase + 3 * 128 + bd);
            float4 aa[4] = {a0, a1, a2, a3};
            float4 bb[4] = {b0, b1, b2, b3};
#pragma unroll
            for (int i = 0; i < 4; ++i)
#pragma unroll
                for (int j = 0; j < 4; ++j) {
                    s4[i][j] = fmaf(aa[i].x, bb[j].x, s4[i][j]);
                    s4[i][j] = fmaf(aa[i].y, bb[j].y, s4[i][j]);
                    s4[i][j] = fmaf(aa[i].z, bb[j].z, s4[i][j]);
                    s4[i][j] = fmaf(aa[i].w, bb[j].w, s4[i][j]);
                }
        }

#pragma unroll
        for (int i = 0; i < 4; ++i) {
#pragma unroll
            for (int j = 0; j < 4; ++j) s4[i][j] *= scale;
            float mt = fmaxf(fmaxf(s4[i][0], s4[i][1]), fmaxf(s4[i][2], s4[i][3]));
            for (int off = 8; off; off >>= 1)
                mt = fmaxf(mt, __shfl_xor_sync(0xffffffffu, mt, off));
            const float mn = fmaxf(m_i[i], mt);
            const float alpha = __expf(m_i[i] - mn);
            m_i[i] = mn;
            float rs = 0.f;
#pragma unroll
            for (int j = 0; j < 4; ++j) {
                s4[i][j] = __expf(s4[i][j] - mn);
                rs += s4[i][j];
            }
            for (int off = 8; off; off >>= 1)
                rs += __shfl_xor_sync(0xffffffffu, rs, off);
            l_i[i] = l_i[i] * alpha + rs;
#pragma unroll
            for (int j = 0; j < 8; ++j) o[i][j] *= alpha;
#pragma unroll
            for (int j = 0; j < 4; ++j)
                Ps[(ty * 4 + i) * 64 + tx * 4 + j] = s4[i][j];
        }
        __syncthreads();

        {
            const float* src = V + (size_t)(kt * 64) * DIMN + h * HD;
#pragma unroll
            for (int it = 0; it < 8; ++it) {
                int idx = tid + it * 256;
                int r = idx >> 5;
                int c = idx & 31;
                float4 v = *(const float4*)(src + (size_t)r * DIMN + (c << 2));
                *(float4*)(KV + r * 128 + ((c ^ ((r >> 2) & 7)) << 2)) = v;
            }
        }
        __syncthreads();

#pragma unroll 4
        for (int k = 0; k < 64; ++k) {
            const int key = (k >> 2) & 7;
            float4 v0 = *(const float4*)(KV + k * 128 + (((tx * 2)     ^ key) << 2));
            float4 v1 = *(const float4*)(KV + k * 128 + (((tx * 2 + 1) ^ key) << 2));
            float p0 = Ps[(ty * 4 + 0) * 64 + k];
            float p1 = Ps[(ty * 4 + 1) * 64 + k];
            float p2 = Ps[(ty * 4 + 2) * 64 + k];
            float p3 = Ps[(ty * 4 + 3) * 64 + k];
            float pv[4] = {p0, p1, p2, p3};
#pragma unroll
            for (int i = 0; i < 4; ++i) {
                o[i][0] = fmaf(pv[i], v0.x, o[i][0]);
                o[i][1] = fmaf(pv[i], v0.y, o[i][1]);
                o[i][2] = fmaf(pv[i], v0.z, o[i][2]);
                o[i][3] = fmaf(pv[i], v0.w, o[i][3]);
                o[i][4] = fmaf(pv[i], v1.x, o[i][4]);
                o[i][5] = fmaf(pv[i], v1.y, o[i][5]);
                o[i][6] = fmaf(pv[i], v1.z, o[i][6]);
                o[i][7] = fmaf(pv[i], v1.w, o[i][7]);
            }
        }
    }

    float* dst = O + (size_t)q0 * DIMN + h * HD;
#pragma unroll
    for (int i = 0; i < 4; ++i) {
        const float inv = 1.0f / l_i[i];
        float4 r0, r1;
        r0.x = o[i][0] * inv; r0.y = o[i][1] * inv;
        r0.z = o[i][2] * inv; r0.w = o[i][3] * inv;
        r1.x = o[i][4] * inv; r1.y = o[i][5] * inv;
        r1.z = o[i][6] * inv; r1.w = o[i][7] * inv;
        float* p = dst + (size_t)(ty * 4 + i) * DIMN + tx * 8;
        *(float4*)p = r0;
        *(float4*)(p + 4) = r1;
    }
}

// ============================================================================
// launch
// ============================================================================
extern "C" void kernel_launch(void* const* d_in, const int* in_sizes, int n_in,
                              void* d_out, int out_size)
{
    const float* x  = (const float*)d_in[0];
    const float* Wq = (const float*)d_in[1];
    const float* bq = (const float*)d_in[2];
    const float* Wk = (const float*)d_in[3];
    const float* bk = (const float*)d_in[4];
    const float* Wv = (const float*)d_in[5];
    const float* bv = (const float*)d_in[6];
    const float* Wo = (const float*)d_in[7];
    const float* bo = (const float*)d_in[8];
    const float* gq = (const float*)d_in[9];
    const float* gk = (const float*)d_in[10];
    const float* cf = (const float*)d_in[11];
    const float* sf = (const float*)d_in[12];
    const float* ch = (const float*)d_in[13];
    const float* sh = (const float*)d_in[14];
    const float* cw = (const float*)d_in[15];
    const float* sw = (const float*)d_in[16];
    float* out = (float*)d_out;

    float *Qd, *Kd, *Vd, *Od;
    unsigned short *xh, *xl, *oh, *ol;
    unsigned short *wqh, *wql, *wkh, *wkl, *wvh, *wvl, *woh, *wol;
    cudaGetSymbolAddress((void**)&Qd, g_Q);
    cudaGetSymbolAddress((void**)&Kd, g_K);
    cudaGetSymbolAddress((void**)&Vd, g_V);
    cudaGetSymbolAddress((void**)&Od, g_O);
    cudaGetSymbolAddress((void**)&xh, g_xh);
    cudaGetSymbolAddress((void**)&xl, g_xl);
    cudaGetSymbolAddress((void**)&oh, g_oh);
    cudaGetSymbolAddress((void**)&ol, g_ol);
    cudaGetSymbolAddress((void**)&wqh, g_wqh);
    cudaGetSymbolAddress((void**)&wql, g_wql);
    cudaGetSymbolAddress((void**)&wkh, g_wkh);
    cudaGetSymbolAddress((void**)&wkl, g_wkl);
    cudaGetSymbolAddress((void**)&wvh, g_wvh);
    cudaGetSymbolAddress((void**)&wvl, g_wvl);
    cudaGetSymbolAddress((void**)&woh, g_woh);
    cudaGetSymbolAddress((void**)&wol, g_wol);

    cudaFuncSetAttribute(flash_kernel,
                         cudaFuncAttributeMaxDynamicSharedMemorySize, FLASH_SMEM);
    cudaFuncSetAttribute(gemm_tc,
                         cudaFuncAttributeMaxDynamicSharedMemorySize, GEMM_SMEM);

    const int NW = DIMN * DIMN;
    const int NXV = S_LEN * DIMN;
    const int NXT = S_PAD * DIMN;

    split_kernel<<<NXT / 512, 256>>>(x, xh, xl, NXV, NXT);
    split_kernel<<<NW / 512, 256>>>(Wq, wqh, wql, NW, NW);
    split_kernel<<<NW / 512, 256>>>(Wk, wkh, wkl, NW, NW);
    split_kernel<<<NW / 512, 256>>>(Wv, wvh, wvl, NW, NW);
    split_kernel<<<NW / 512, 256>>>(Wo, woh, wol, NW, NW);

    dim3 ggrid(DIMN / 128, S_PAD / 128);
    gemm_tc<<<ggrid, 256, GEMM_SMEM>>>(xh, xl, wqh, wql, bq, Qd, S_PAD);
    gemm_tc<<<ggrid, 256, GEMM_SMEM>>>(xh, xl, wkh, wkl, bk, Kd, S_PAD);
    gemm_tc<<<ggrid, 256, GEMM_SMEM>>>(xh, xl, wvh, wvl, bv, Vd, S_PAD);

    rmsrope_kernel<<<S_LEN, 256>>>(Qd, Kd, gq, gk, cf, sf, ch, sh, cw, sw);

    flash_kernel<<<dim3(S_LEN / 64, NHEAD), 256, FLASH_SMEM>>>(Qd, Kd, Vd, Od);

    split_kernel<<<NXT / 512, 256>>>(Od, oh, ol, NXV, NXT);
    gemm_tc<<<ggrid, 256, GEMM_SMEM>>>(oh, ol, woh, wol, bo, out, S_LEN);
}

// round 5
// speedup vs baseline: 3.0071x; 1.9706x over previous
#include <cuda_runtime.h>
#include <cuda_bf16.h>
#include <cstdint>
#include <math.h>

// ---------------- problem constants ----------------
#define S_LEN 4032
#define S_PAD 4096
#define DIMN  1536
#define NHEAD 12
#define HD    128
#define FF    9
#define HHG   16
#define WWG   28
#define CF    22
#define CHH   21
#define CWW   21

// softmax scale folded with log2(e), folded into Q at rmsrope time
#define QK_SCALE_LOG2E ((float)(1.4426950408889634 * 0.08838834764831845))

// ---------------- scratch ----------------
__device__ float g_Q[S_PAD * DIMN];
__device__ float g_K[S_PAD * DIMN];
__device__ unsigned short g_qh[S_PAD * DIMN], g_ql[S_PAD * DIMN];
__device__ unsigned short g_kh[S_PAD * DIMN], g_kl[S_PAD * DIMN];
__device__ unsigned short g_vh[S_PAD * DIMN], g_vl[S_PAD * DIMN];
__device__ unsigned short g_oh[S_PAD * DIMN], g_ol[S_PAD * DIMN];
__device__ unsigned short g_xh[S_PAD * DIMN], g_xl[S_PAD * DIMN];
__device__ unsigned short g_wqh[DIMN * DIMN], g_wql[DIMN * DIMN];
__device__ unsigned short g_wkh[DIMN * DIMN], g_wkl[DIMN * DIMN];
__device__ unsigned short g_wvh[DIMN * DIMN], g_wvl[DIMN * DIMN];
__device__ unsigned short g_woh[DIMN * DIMN], g_wol[DIMN * DIMN];

// ---------------- helpers ----------------
__device__ __forceinline__ uint32_t smem_to_u32(const void* p) {
    uint32_t a;
    asm("{ .reg .u64 t; cvta.to.shared.u64 t, %1; cvt.u32.u64 %0, t; }" : "=r"(a) : "l"(p));
    return a;
}
#define SWZ128(off) ((off) ^ (((off) >> 3) & 0x70))

__device__ __forceinline__ void ldsm_x4(uint32_t* r, uint32_t addr) {
    asm volatile("ldmatrix.sync.aligned.m8n8.x4.shared.b16 {%0,%1,%2,%3}, [%4];"
                 : "=r"(r[0]), "=r"(r[1]), "=r"(r[2]), "=r"(r[3]) : "r"(addr));
}
__device__ __forceinline__ void ldsm_x2(uint32_t* r, uint32_t addr) {
    asm volatile("ldmatrix.sync.aligned.m8n8.x2.shared.b16 {%0,%1}, [%2];"
                 : "=r"(r[0]), "=r"(r[1]) : "r"(addr));
}
__device__ __forceinline__ void ldsm_x2_t(uint32_t* r, uint32_t addr) {
    asm volatile("ldmatrix.sync.aligned.m8n8.x2.trans.shared.b16 {%0,%1}, [%2];"
                 : "=r"(r[0]), "=r"(r[1]) : "r"(addr));
}
__device__ __forceinline__ void mma_bf16(float* c, const uint32_t* a, const uint32_t* b) {
    asm volatile("mma.sync.aligned.m16n8k16.row.col.f32.bf16.bf16.f32 "
                 "{%0,%1,%2,%3}, {%4,%5,%6,%7}, {%8,%9}, {%0,%1,%2,%3};"
                 : "+f"(c[0]), "+f"(c[1]), "+f"(c[2]), "+f"(c[3])
                 : "r"(a[0]), "r"(a[1]), "r"(a[2]), "r"(a[3]), "r"(b[0]), "r"(b[1]));
}
__device__ __forceinline__ float ex2f(float x) {
    float y; asm("ex2.approx.f32 %0, %1;" : "=f"(y) : "f"(x)); return y;
}
// pack (lo=x, hi=y) into bf16x2
__device__ __forceinline__ uint32_t pack_bf2(float x, float y) {
    uint32_t d; asm("cvt.rn.bf16x2.f32 %0, %1, %2;" : "=r"(d) : "f"(y), "f"(x)); return d;
}
// split two floats into hi/lo bf16x2 words
__device__ __forceinline__ void split2(float x, float y, uint32_t& hi, uint32_t& lo) {
    hi = pack_bf2(x, y);
    float hx = __uint_as_float(hi << 16);
    float hy = __uint_as_float(hi & 0xffff0000u);
    lo = pack_bf2(x - hx, y - hy);
}
__device__ __forceinline__ void cp_async16(uint32_t saddr, const void* g) {
    asm volatile("cp.async.cg.shared.global [%0], [%1], 16;" :: "r"(saddr), "l"(g) : "memory");
}

// ============================================================================
// split fp32 -> bf16 hi/lo (zero padding beyond n_valid)
// ============================================================================
__global__ __launch_bounds__(256) void split_kernel(
    const float* __restrict__ src, unsigned short* __restrict__ hi,
    unsigned short* __restrict__ lo, int n_valid, int n_total)
{
    int i = (blockIdx.x * 256 + threadIdx.x) * 2;
    if (i >= n_total) return;
    float2 v = (i < n_valid) ? *(const float2*)(src + i) : make_float2(0.f, 0.f);
    uint32_t h, l;
    split2(v.x, v.y, h, l);
    *(unsigned int*)(hi + i) = h;
    *(unsigned int*)(lo + i) = l;
}

// ============================================================================
// mma.sync bf16x3 GEMM: C[M,N] = A[M,K] @ B[N,K]^T + bias
// optional bf16 hi/lo output (Chi/Clo non-null) instead of fp32 C
// ============================================================================
#define SM_AH  0
#define SM_AL  16384
#define SM_BH  32768
#define SM_BL  49152
#define GEMM_SMEM 65536
#define NCHUNK (DIMN / 64)

__global__ __launch_bounds__(256, 2) void gemm_tc(
    const unsigned short* __restrict__ Ahi, const unsigned short* __restrict__ Alo,
    const unsigned short* __restrict__ Bhi, const unsigned short* __restrict__ Blo,
    const float* __restrict__ bias, float* __restrict__ C,
    unsigned short* __restrict__ Chi, unsigned short* __restrict__ Clo, int Mvalid)
{
    extern __shared__ __align__(1024) char smem[];
    const uint32_t sb = smem_to_u32(smem);
    const int tid  = threadIdx.x;
    const int lane = tid & 31;
    const int wid  = tid >> 5;
    const int wm   = wid & 1;
    const int wn   = wid >> 1;
    const int bm = blockIdx.y * 128;
    const int bn = blockIdx.x * 128;

    const int r0 = tid >> 3;
    const int c8 = tid & 7;
    const uint32_t st_off = SWZ128((uint32_t)(r0 * 128 + c8 * 16));

    uint32_t aoff[4], akey[4];
#pragma unroll
    for (int mf = 0; mf < 4; ++mf) {
        int arow = wm * 64 + mf * 16 + (lane & 15);
        aoff[mf] = (uint32_t)(arow * 128);
        akey[mf] = (uint32_t)((arow & 7) << 4);
    }
    uint32_t boff[4], bkey[4];
    {
        int l = lane & 15;
#pragma unroll
        for (int nf = 0; nf < 4; ++nf) {
            int brow = wn * 32 + nf * 8 + (l & 7);
            boff[nf] = (uint32_t)(brow * 128);
            bkey[nf] = (uint32_t)((brow & 7) << 4);
        }
    }
    const uint32_t abit = (uint32_t)((lane >> 4) << 4);
    const uint32_t bbit = (uint32_t)((((lane & 15) >> 3) & 1) << 4);

    float acc[4][4][4];
#pragma unroll
    for (int mf = 0; mf < 4; ++mf)
#pragma unroll
        for (int nf = 0; nf < 4; ++nf)
#pragma unroll
            for (int e = 0; e < 4; ++e) acc[mf][nf][e] = 0.f;

    for (int chunk = 0; chunk < NCHUNK; ++chunk) {
        const int k0 = chunk * 64;
        __syncthreads();
        {
            const unsigned short* srcs[4] = {Ahi, Alo, Bhi, Blo};
            const int rowbase[4] = {bm, bm, bn, bn};
            const uint32_t dsts[4] = {SM_AH, SM_AL, SM_BH, SM_BL};
#pragma unroll
            for (int t = 0; t < 4; ++t) {
                const unsigned short* s = srcs[t] + (size_t)(rowbase[t] + r0) * DIMN + k0 + c8 * 8;
                char* d = smem + dsts[t] + st_off;
#pragma unroll
                for (int i = 0; i < 4; ++i)
                    *(uint4*)(d + i * 4096) = *(const uint4*)(s + (size_t)(i * 32) * DIMN);
            }
        }
        __syncthreads();

#pragma unroll
        for (int ks = 0; ks < 4; ++ks) {
            const uint32_t kb = (uint32_t)(ks * 32);
            uint32_t bh[4][2], bl[4][2];
#pragma unroll
            for (int nf = 0; nf < 4; ++nf) {
                uint32_t ad = sb + SM_BH + boff[nf] + ((kb + bbit) ^ bkey[nf]);
                ldsm_x2(bh[nf], ad);
                ldsm_x2(bl[nf], ad + (SM_BL - SM_BH));
            }
#pragma unroll
            for (int mf = 0; mf < 4; ++mf) {
                uint32_t ah[4], al[4];
                uint32_t ad = sb + SM_AH + aoff[mf] + ((kb + abit) ^ akey[mf]);
                ldsm_x4(ah, ad);
                ldsm_x4(al, ad + (SM_AL - SM_AH));
#pragma unroll
                for (int nf = 0; nf < 4; ++nf) {
                    mma_bf16(acc[mf][nf], ah, bh[nf]);
                    mma_bf16(acc[mf][nf], ah, bl[nf]);
                    mma_bf16(acc[mf][nf], al, bh[nf]);
                }
            }
        }
    }

    // ---- epilogue ----
    const int row0 = bm + wm * 64 + (lane >> 2);
    const int col0 = bn + wn * 32 + (lane & 3) * 2;
#pragma unroll
    for (int nf = 0; nf < 4; ++nf) {
        const int c = col0 + nf * 8;
        const float2 bb = *(const float2*)(bias + c);
#pragma unroll
        for (int mf = 0; mf < 4; ++mf) {
            const int r = row0 + mf * 16;
            if (Chi) {
                uint32_t h, l;
                if (r < Mvalid) {
                    split2(acc[mf][nf][0] + bb.x, acc[mf][nf][1] + bb.y, h, l);
                    *(unsigned int*)(Chi + (size_t)r * DIMN + c) = h;
                    *(unsigned int*)(Clo + (size_t)r * DIMN + c) = l;
                }
                if (r + 8 < Mvalid) {
                    split2(acc[mf][nf][2] + bb.x, acc[mf][nf][3] + bb.y, h, l);
                    *(unsigned int*)(Chi + (size_t)(r + 8) * DIMN + c) = h;
                    *(unsigned int*)(Clo + (size_t)(r + 8) * DIMN + c) = l;
                }
            } else {
                if (r < Mvalid) {
                    float2 v; v.x = acc[mf][nf][0] + bb.x; v.y = acc[mf][nf][1] + bb.y;
                    *(float2*)(C + (size_t)r * DIMN + c) = v;
                }
                if (r + 8 < Mvalid) {
                    float2 v; v.x = acc[mf][nf][2] + bb.x; v.y = acc[mf][nf][3] + bb.y;
                    *(float2*)(C + (size_t)(r + 8) * DIMN + c) = v;
                }
            }
        }
    }
}

// ============================================================================
// Fused RMSNorm + 3D RoPE; emits bf16 hi/lo Q (pre-scaled) and K
// ============================================================================
__global__ __launch_bounds__(256) void rmsrope_kernel(
    const float* __restrict__ Qm, const float* __restrict__ Km,
    const float* __restrict__ gq, const float* __restrict__ gk,
    const float* __restrict__ cf, const float* __restrict__ sf,
    const float* __restrict__ ch, const float* __restrict__ sh,
    const float* __restrict__ cw, const float* __restrict__ sw,
    unsigned short* __restrict__ qh, unsigned short* __restrict__ ql,
    unsigned short* __restrict__ kh, unsigned short* __restrict__ kl)
{
    const int s = blockIdx.x;
    const int tid = threadIdx.x;
    const int f  = s / (HHG * WWG);
    const int rm = s - f * (HHG * WWG);
    const int hh = rm / WWG;
    const int ww = rm - hh * WWG;

    float co[3], si[3];
#pragma unroll
    for (int p = 0; p < 3; ++p) {
        int c = (tid * 3 + p) & 63;
        if (c < CF)            { co[p] = cf[f  * CF  + c];              si[p] = sf[f  * CF  + c]; }
        else if (c < CF + CHH) { co[p] = ch[hh * CHH + (c - CF)];       si[p] = sh[hh * CHH + (c - CF)]; }
        else                   { co[p] = cw[ww * CWW + (c - CF - CHH)]; si[p] = sw[ww * CWW + (c - CF - CHH)]; }
    }

    __shared__ float red[8];
    __shared__ float bcast;

    for (int which = 0; which < 2; ++which) {
        const float* T = which ? Km : Qm;
        const float* g = which ? gk : gq;
        unsigned short* oh = which ? kh : qh;
        unsigned short* ol = which ? kl : ql;
        const float post = which ? 1.0f : QK_SCALE_LOG2E;
        const size_t base = (size_t)s * DIMN + tid * 6;

        float v[6];
#pragma unroll
        for (int p = 0; p < 3; ++p) {
            float2 t = *(const float2*)(T + base + 2 * p);
            v[2 * p] = t.x; v[2 * p + 1] = t.y;
        }
        float ss = 0.f;
#pragma unroll
        for (int e = 0; e < 6; ++e) ss += v[e] * v[e];
        for (int off = 16; off; off >>= 1) ss += __shfl_xor_sync(0xffffffffu, ss, off);
        if ((tid & 31) == 0) red[tid >> 5] = ss;
        __syncthreads();
        if (tid < 32) {
            float t = (tid < 8) ? red[tid] : 0.f;
            for (int off = 4; off; off >>= 1) t += __shfl_xor_sync(0xffffffffu, t, off);
            if (tid == 0) bcast = t;
        }
        __syncthreads();
        const float rinv = rsqrtf(bcast * (1.0f / DIMN) + 1e-6f);

#pragma unroll
        for (int p = 0; p < 3; ++p) {
            float e = v[2 * p]     * rinv * g[tid * 6 + 2 * p];
            float o = v[2 * p + 1] * rinv * g[tid * 6 + 2 * p + 1];
            float rx = (e * co[p] - o * si[p]) * post;
            float ry = (e * si[p] + o * co[p]) * post;
            uint32_t hw, lw;
            split2(rx, ry, hw, lw);
            *(unsigned int*)(oh + base + 2 * p) = hw;
            *(unsigned int*)(ol + base + 2 * p) = lw;
        }
        __syncthreads();
    }
}

// ============================================================================
// Flash attention, HMMA bf16x3. BQ=128 (8 warps x m16), BK=64, D=128.
// smem: 2 stages x (KH,KL,VH,VL), each tile 64 rows x 128 cols bf16 stored as
// two 8KB chunks of [64 rows][64 cols], 128B rows, SWZ128. Total 128KB.
// ============================================================================
#define FLASH_SMEM 131072
#define T_KH 0
#define T_KL 16384
#define T_VH 32768
#define T_VL 49152

__global__ __launch_bounds__(256, 1) void flash_tc(
    const unsigned short* __restrict__ qh_, const unsigned short* __restrict__ ql_,
    const unsigned short* __restrict__ kh_, const unsigned short* __restrict__ kl_,
    const unsigned short* __restrict__ vh_, const unsigned short* __restrict__ vl_,
    unsigned short* __restrict__ oh_, unsigned short* __restrict__ ol_)
{
    extern __shared__ __align__(1024) char sm[];
    const uint32_t sb = smem_to_u32(sm);
    const int tid = threadIdx.x;
    const int lane = tid & 31;
    const int w = tid >> 5;
    const int l15 = lane & 15;
    const int h = blockIdx.y;
    const int q0 = blockIdx.x * 128;

    // ---- stage Q (hi/lo) into smem bytes [0,64K) ----
    {
        const unsigned short* srcs[2] = {qh_, ql_};
#pragma unroll
        for (int hl = 0; hl < 2; ++hl) {
            const unsigned short* s = srcs[hl];
#pragma unroll
            for (int i = 0; i < 8; ++i) {
                int idx = tid + i * 256;
                int qr = idx >> 4, c16 = idx & 15;
                uint4 v = *(const uint4*)(s + (size_t)(q0 + qr) * DIMN + h * HD + c16 * 8);
                uint32_t off = (uint32_t)((qr >> 6) * 32768 + hl * 16384 + (c16 >> 3) * 8192)
                             + SWZ128((uint32_t)((qr & 63) * 128 + (c16 & 7) * 16));
                *(uint4*)(sm + off) = v;
            }
        }
    }
    __syncthreads();

    // ---- Q to registers: qa[hilo][kstep][4] ----
    uint32_t qa[2][8][4];
    {
        int qr = w * 16 + l15;
        uint32_t tilebase = (uint32_t)((qr >> 6) * 32768);
        uint32_t rowb = (uint32_t)((qr & 63) * 128);
#pragma unroll
        for (int hl = 0; hl < 2; ++hl)
#pragma unroll
            for (int ks = 0; ks < 8; ++ks) {
                uint32_t c8 = (uint32_t)((ks & 3) * 2 + (lane >> 4));
                uint32_t addr = sb + tilebase + (uint32_t)(hl * 16384 + (ks >> 2) * 8192)
                              + SWZ128(rowb + c8 * 16);
                ldsm_x4(qa[hl][ks], addr);
            }
    }
    __syncthreads();

    // ---- K/V stage loader ----
    const int lr = tid >> 2;          // 0..63
    const int lq = tid & 3;
    auto issue_stage = [&](int kt, int st) {
        const int key0 = kt * 64;
        const unsigned short* srcs[4] = {kh_, kl_, vh_, vl_};
        uint32_t base = (uint32_t)(st * 65536);
#pragma unroll
        for (int t = 0; t < 4; ++t) {
            const unsigned short* sp = srcs[t] + (size_t)(key0 + lr) * DIMN + h * HD;
#pragma unroll
            for (int i = 0; i < 4; ++i) {
                int c16 = lq * 4 + i;
                uint32_t saddr = sb + base + (uint32_t)(t * 16384 + (c16 >> 3) * 8192)
                               + SWZ128((uint32_t)(lr * 128 + (c16 & 7) * 16));
                cp_async16(saddr, sp + c16 * 8);
            }
        }
        asm volatile("cp.async.commit_group;" ::: "memory");
    };

    float oacc[16][4];
#pragma unroll
    for (int nt = 0; nt < 16; ++nt)
#pragma unroll
        for (int e = 0; e < 4; ++e) oacc[nt][e] = 0.f;
    float mrow0 = -1e30f, mrow1 = -1e30f, lrow0 = 0.f, lrow1 = 0.f;

    issue_stage(0, 0);

    for (int kt = 0; kt < 63; ++kt) {
        const int st = kt & 1;
        if (kt < 62) {
            issue_stage(kt + 1, st ^ 1);
            asm volatile("cp.async.wait_group 1;" ::: "memory");
        } else {
            asm volatile("cp.async.wait_group 0;" ::: "memory");
        }
        __syncthreads();

        const uint32_t stb = sb + (uint32_t)(st * 65536);

        // ---- scores ----
        float sc[8][4];
#pragma unroll
        for (int nt = 0; nt < 8; ++nt)
#pragma unroll
            for (int e = 0; e < 4; ++e) sc[nt][e] = 0.f;

#pragma unroll
        for (int ks = 0; ks < 8; ++ks) {
            const uint32_t kchunk = (uint32_t)((ks >> 2) * 8192);
            const uint32_t kc8 = (uint32_t)(((ks & 3) * 2 + ((l15 >> 3) & 1)) * 16);
#pragma unroll
            for (int nt = 0; nt < 8; ++nt) {
                uint32_t addr = stb + T_KH + kchunk
                              + SWZ128((uint32_t)((nt * 8 + (l15 & 7)) * 128) + kc8);
                uint32_t bh[2], bl[2];
                ldsm_x2(bh, addr);
                ldsm_x2(bl, addr + (T_KL - T_KH));
                mma_bf16(sc[nt], qa[0][ks], bh);
                mma_bf16(sc[nt], qa[0][ks], bl);
                mma_bf16(sc[nt], qa[1][ks], bh);
            }
        }

        // ---- online softmax (scores already in log2 units) ----
        float mx0 = -1e30f, mx1 = -1e30f;
#pragma unroll
        for (int nt = 0; nt < 8; ++nt) {
            mx0 = fmaxf(mx0, fmaxf(sc[nt][0], sc[nt][1]));
            mx1 = fmaxf(mx1, fmaxf(sc[nt][2], sc[nt][3]));
        }
        mx0 = fmaxf(mx0, __shfl_xor_sync(0xffffffffu, mx0, 1));
        mx0 = fmaxf(mx0, __shfl_xor_sync(0xffffffffu, mx0, 2));
        mx1 = fmaxf(mx1, __shfl_xor_sync(0xffffffffu, mx1, 1));
        mx1 = fmaxf(mx1, __shfl_xor_sync(0xffffffffu, mx1, 2));
        const float mn0 = fmaxf(mrow0, mx0);
        const float mn1 = fmaxf(mrow1, mx1);
        const float al0 = ex2f(mrow0 - mn0);
        const float al1 = ex2f(mrow1 - mn1);
        mrow0 = mn0; mrow1 = mn1;
        float rs0 = 0.f, rs1 = 0.f;
#pragma unroll
        for (int nt = 0; nt < 8; ++nt) {
            sc[nt][0] = ex2f(sc[nt][0] - mn0); rs0 += sc[nt][0];
            sc[nt][1] = ex2f(sc[nt][1] - mn0); rs0 += sc[nt][1];
            sc[nt][2] = ex2f(sc[nt][2] - mn1); rs1 += sc[nt][2];
            sc[nt][3] = ex2f(sc[nt][3] - mn1); rs1 += sc[nt][3];
        }
        rs0 += __shfl_xor_sync(0xffffffffu, rs0, 1);
        rs0 += __shfl_xor_sync(0xffffffffu, rs0, 2);
        rs1 += __shfl_xor_sync(0xffffffffu, rs1, 1);
        rs1 += __shfl_xor_sync(0xffffffffu, rs1, 2);
        lrow0 = lrow0 * al0 + rs0;
        lrow1 = lrow1 * al1 + rs1;
#pragma unroll
        for (int nt = 0; nt < 16; ++nt) {
            oacc[nt][0] *= al0; oacc[nt][1] *= al0;
            oacc[nt][2] *= al1; oacc[nt][3] *= al1;
        }

        // ---- pack P into A operands (hi/lo) ----
        uint32_t pah[4][4], pal[4][4];
#pragma unroll
        for (int t = 0; t < 4; ++t) {
#pragma unroll
            for (int half = 0; half < 2; ++half) {
                const int nt = 2 * t + half;
                split2(sc[nt][0], sc[nt][1], pah[t][half * 2 + 0], pal[t][half * 2 + 0]);
                split2(sc[nt][2], sc[nt][3], pah[t][half * 2 + 1], pal[t][half * 2 + 1]);
            }
        }

        // ---- O += P @ V ----
#pragma unroll
        for (int t = 0; t < 4; ++t) {
            const uint32_t vrow = (uint32_t)((t * 16 + ((l15 >> 3) & 1) * 8 + (l15 & 7)) * 128);
#pragma unroll
            for (int nt = 0; nt < 16; ++nt) {
                uint32_t addr = stb + T_VH + (uint32_t)((nt >> 3) * 8192)
                              + SWZ128(vrow + (uint32_t)((nt & 7) * 16));
                uint32_t bh[2], bl[2];
                ldsm_x2_t(bh, addr);
                ldsm_x2_t(bl, addr + (T_VL - T_VH));
                mma_bf16(oacc[nt], pah[t], bh);
                mma_bf16(oacc[nt], pah[t], bl);
                mma_bf16(oacc[nt], pal[t], bh);
            }
        }
        __syncthreads();
    }

    // ---- epilogue: O/l -> bf16 hi/lo ----
    const float inv0 = 1.0f / lrow0;
    const float inv1 = 1.0f / lrow1;
    const int r0 = q0 + w * 16 + (lane >> 2);
    const int cbase = h * HD + (lane & 3) * 2;
#pragma unroll
    for (int nt = 0; nt < 16; ++nt) {
        const int c = cbase + nt * 8;
        if (r0 < S_LEN) {
            uint32_t hw, lw;
            split2(oacc[nt][0] * inv0, oacc[nt][1] * inv0, hw, lw);
            *(unsigned int*)(oh_ + (size_t)r0 * DIMN + c) = hw;
            *(unsigned int*)(ol_ + (size_t)r0 * DIMN + c) = lw;
        }
        if (r0 + 8 < S_LEN) {
            uint32_t hw, lw;
            split2(oacc[nt][2] * inv1, oacc[nt][3] * inv1, hw, lw);
            *(unsigned int*)(oh_ + (size_t)(r0 + 8) * DIMN + c) = hw;
            *(unsigned int*)(ol_ + (size_t)(r0 + 8) * DIMN + c) = lw;
        }
    }
}

// ============================================================================
// launch
// ============================================================================
extern "C" void kernel_launch(void* const* d_in, const int* in_sizes, int n_in,
                              void* d_out, int out_size)
{
    const float* x  = (const float*)d_in[0];
    const float* Wq = (const float*)d_in[1];
    const float* bq = (const float*)d_in[2];
    const float* Wk = (const float*)d_in[3];
    const float* bk = (const float*)d_in[4];
    const float* Wv = (const float*)d_in[5];
    const float* bv = (const float*)d_in[6];
    const float* Wo = (const float*)d_in[7];
    const float* bo = (const float*)d_in[8];
    const float* gq = (const float*)d_in[9];
    const float* gk = (const float*)d_in[10];
    const float* cf = (const float*)d_in[11];
    const float* sf = (const float*)d_in[12];
    const float* ch = (const float*)d_in[13];
    const float* sh = (const float*)d_in[14];
    const float* cw = (const float*)d_in[15];
    const float* sw = (const float*)d_in[16];
    float* out = (float*)d_out;

    float *Qd, *Kd;
    unsigned short *qh, *ql, *kh, *kl, *vh, *vl, *oh, *ol, *xh, *xl;
    unsigned short *wqh, *wql, *wkh, *wkl, *wvh, *wvl, *woh, *wol;
    cudaGetSymbolAddress((void**)&Qd, g_Q);
    cudaGetSymbolAddress((void**)&Kd, g_K);
    cudaGetSymbolAddress((void**)&qh, g_qh);  cudaGetSymbolAddress((void**)&ql, g_ql);
    cudaGetSymbolAddress((void**)&kh, g_kh);  cudaGetSymbolAddress((void**)&kl, g_kl);
    cudaGetSymbolAddress((void**)&vh, g_vh);  cudaGetSymbolAddress((void**)&vl, g_vl);
    cudaGetSymbolAddress((void**)&oh, g_oh);  cudaGetSymbolAddress((void**)&ol, g_ol);
    cudaGetSymbolAddress((void**)&xh, g_xh);  cudaGetSymbolAddress((void**)&xl, g_xl);
    cudaGetSymbolAddress((void**)&wqh, g_wqh); cudaGetSymbolAddress((void**)&wql, g_wql);
    cudaGetSymbolAddress((void**)&wkh, g_wkh); cudaGetSymbolAddress((void**)&wkl, g_wkl);
    cudaGetSymbolAddress((void**)&wvh, g_wvh); cudaGetSymbolAddress((void**)&wvl, g_wvl);
    cudaGetSymbolAddress((void**)&woh, g_woh); cudaGetSymbolAddress((void**)&wol, g_wol);

    cudaFuncSetAttribute(gemm_tc,
                         cudaFuncAttributeMaxDynamicSharedMemorySize, GEMM_SMEM);
    cudaFuncSetAttribute(flash_tc,
                         cudaFuncAttributeMaxDynamicSharedMemorySize, FLASH_SMEM);

    const int NW = DIMN * DIMN;
    const int NXV = S_LEN * DIMN;
    const int NXT = S_PAD * DIMN;

    split_kernel<<<NXT / 512, 256>>>(x, xh, xl, NXV, NXT);
    split_kernel<<<NW / 512, 256>>>(Wq, wqh, wql, NW, NW);
    split_kernel<<<NW / 512, 256>>>(Wk, wkh, wkl, NW, NW);
    split_kernel<<<NW / 512, 256>>>(Wv, wvh, wvl, NW, NW);
    split_kernel<<<NW / 512, 256>>>(Wo, woh, wol, NW, NW);

    dim3 ggrid(DIMN / 128, S_PAD / 128);
    gemm_tc<<<ggrid, 256, GEMM_SMEM>>>(xh, xl, wqh, wql, bq, Qd, nullptr, nullptr, S_PAD);
    gemm_tc<<<ggrid, 256, GEMM_SMEM>>>(xh, xl, wkh, wkl, bk, Kd, nullptr, nullptr, S_PAD);
    gemm_tc<<<ggrid, 256, GEMM_SMEM>>>(xh, xl, wvh, wvl, bv, nullptr, vh, vl, S_PAD);

    rmsrope_kernel<<<S_LEN, 256>>>(Qd, Kd, gq, gk, cf, sf, ch, sh, cw, sw,
                                   qh, ql, kh, kl);

    flash_tc<<<dim3(S_PAD / 128, NHEAD), 256, FLASH_SMEM>>>(qh, ql, kh, kl, vh, vl, oh, ol);

    gemm_tc<<<ggrid, 256, GEMM_SMEM>>>(oh, ol, woh, wol, bo, out, nullptr, nullptr, S_LEN);
}